// round 6
// baseline (speedup 1.0000x reference)
#include <cuda_runtime.h>
#include <float.h>
#include <math.h>

// Problem constants (from reference)
#define BEV_N   200          // BEV_H == BEV_W == 200
#define IMG_H   128
#define IMG_W   352
#define NCH     32
#define NB      2            // batch
#define NCAM    6            // cameras per batch
#define BNMAT   (NB*NCAM)    // 12 projection matrices
#define NCELL   (NB*BEV_N*BEV_N)   // 80,000
#define CELLS_PER_BLOCK 32   // 256 threads / 8 lanes-per-cell
#define ROWSTRIDE (IMG_W * (NCH/4))

// One fused kernel:
//  Phase 0: reduced P = (K@RT) rows 0..2, cols {0,1,3} into smem (z==0 plane)
//  Phase 1: one thread per (cell,cam); warp-local ballot-compaction of valid cams
//  Phase 2: 8 lanes/cell (float4 channels), depth-1 software-pipelined sampling
__global__ __launch_bounds__(256) void ipm_fused_kernel(const float* __restrict__ images,
                                                        const float* __restrict__ Ks,
                                                        const float* __restrict__ RTs,
                                                        float* __restrict__ out) {
    __shared__ float  sP[BNMAT][9];
    __shared__ float4 sW[CELLS_PER_BLOCK * NCAM];     // (w00,w01,w10,w11)
    __shared__ int    sBase[CELLS_PER_BLOCK * NCAM];  // float4-index of im00

    const int t = threadIdx.x;

    // ---------- Phase 0: projection matrices ----------
    if (t < BNMAT * 9) {
        const int m  = t / 9;
        const int e  = t - m * 9;
        const int r  = e / 3;
        const int ci = e - r * 3;
        const int c  = (ci == 2) ? 3 : ci;
        const float* K  = Ks  + m * 16 + r * 4;
        const float* RT = RTs + m * 16;
        sP[m][e] = K[0] * RT[c] + K[1] * RT[4 + c]
                 + K[2] * RT[8 + c] + K[3] * RT[12 + c];
    }
    __syncthreads();

    const int cell0 = blockIdx.x * CELLS_PER_BLOCK;   // grid is exactly 2500 blocks
    const int lc    = t >> 3;                          // local cell 0..31
    const int sub   = t & 7;                           // lane-in-cell / cam slot

    // ---------- Phase 1: project + warp-local compaction of valid cameras ----------
    int n;                                             // valid-cam count for this cell
    {
        const int cam  = sub;                          // cams 0..5 active, 6..7 idle
        const int cell = cell0 + lc;
        bool valid = false;
        float4 w = make_float4(0.f, 0.f, 0.f, 0.f);
        int baseIdx = 0;

        if (cam < NCAM) {
            const int b   = cell / (BEV_N * BEV_N);
            const int rem = cell - b * (BEV_N * BEV_N);
            const int i   = rem / BEV_N;
            const int j   = rem - i * BEV_N;
            // linspace(-50,50,200) evaluated in float64 like numpy, rounded to fp32
            const float y = (float)(-50.0 + (double)i * (100.0 / 199.0));
            const float x = (float)(-50.0 + (double)j * (100.0 / 199.0));

            const int bn = b * NCAM + cam;
            const float* P = sP[bn];
            const float pc0 = P[0] * y + P[1] * x + P[2];
            const float pc1 = P[3] * y + P[4] * x + P[5];
            const float pc2 = P[6] * y + P[7] * x + P[8];
            const float inv = 1.0f / (pc2 + 1e-7f);
            const float fx = pc0 * inv;
            const float fy = pc1 * inv;

            // Outside [0,W-1) x [0,H-1): clamped bilinear collapses => exact 0
            if (fx >= 0.0f && fx < (float)(IMG_W - 1) &&
                fy >= 0.0f && fy < (float)(IMG_H - 1)) {
                valid = true;
                const float x0f = floorf(fx);
                const float y0f = floorf(fy);
                const float wx1 = fx - x0f, wx0 = 1.0f - wx1;
                const float wy1 = fy - y0f, wy0 = 1.0f - wy1;
                w = make_float4(wx0 * wy0, wx0 * wy1, wx1 * wy0, wx1 * wy1);
                baseIdx = (((int)(bn * IMG_H) + (int)y0f) * IMG_W + (int)x0f) * (NCH / 4);
            }
        }

        const unsigned ball = __ballot_sync(0xFFFFFFFFu, valid);
        const int laneBase  = (t & 31) & ~7;                      // first lane of 8-group
        const unsigned grp  = (ball >> laneBase) & 0xFFu;
        if (valid) {
            const int slot = __popc(grp & ((1u << sub) - 1u));    // cam-ordered slot
            sW[lc * NCAM + slot]    = w;
            sBase[lc * NCAM + slot] = baseIdx;
        }
        n = (int)__popc(grp);
    }
    __syncwarp();   // phase 1 writes and phase 2 reads are warp-local (same 4 cells)

    // ---------- Phase 2: pipelined sampling over valid cams, max-reduce ----------
    // If every cam is valid the result is max over 6 samples; otherwise some cam
    // contributes an exact 0 (clamp-collapsed weights), so seed with 0.
    float4 best = (n == NCAM)
        ? make_float4(-FLT_MAX, -FLT_MAX, -FLT_MAX, -FLT_MAX)
        : make_float4(0.f, 0.f, 0.f, 0.f);

    const float4* __restrict__ img4 = (const float4*)images;
    const int slot0 = lc * NCAM;

    if (n > 0) {
        float4 w   = sW[slot0];
        int   base = sBase[slot0] + sub;
        float4 c00 = __ldg(img4 + base);
        float4 c10 = __ldg(img4 + base + (NCH / 4));
        float4 c01 = __ldg(img4 + base + ROWSTRIDE);
        float4 c11 = __ldg(img4 + base + ROWSTRIDE + (NCH / 4));

        #pragma unroll 1
        for (int k = 1; k <= n; k++) {
            const bool more = (k < n);
            float4 nw;
            float4 p00, p10, p01, p11;
            if (more) {                       // prefetch next cam while current in flight
                nw = sW[slot0 + k];
                const int nb = sBase[slot0 + k] + sub;
                p00 = __ldg(img4 + nb);
                p10 = __ldg(img4 + nb + (NCH / 4));
                p01 = __ldg(img4 + nb + ROWSTRIDE);
                p11 = __ldg(img4 + nb + ROWSTRIDE + (NCH / 4));
            }

            float4 v;
            v.x = w.x * c00.x + w.y * c01.x + w.z * c10.x + w.w * c11.x;
            v.y = w.x * c00.y + w.y * c01.y + w.z * c10.y + w.w * c11.y;
            v.z = w.x * c00.z + w.y * c01.z + w.z * c10.z + w.w * c11.z;
            v.w = w.x * c00.w + w.y * c01.w + w.z * c10.w + w.w * c11.w;
            best.x = fmaxf(best.x, v.x);
            best.y = fmaxf(best.y, v.y);
            best.z = fmaxf(best.z, v.z);
            best.w = fmaxf(best.w, v.w);

            if (more) {
                w = nw;
                c00 = p00; c10 = p10; c01 = p01; c11 = p11;
            }
        }
    }

    ((float4*)out)[(size_t)(cell0 + lc) * (NCH / 4) + sub] = best;
}

extern "C" void kernel_launch(void* const* d_in, const int* in_sizes, int n_in,
                              void* d_out, int out_size) {
    const float* images = (const float*)d_in[0];
    const float* Ks     = (const float*)d_in[1];
    const float* RTs    = (const float*)d_in[2];
    float* out = (float*)d_out;

    const int nblocks = NCELL / CELLS_PER_BLOCK;   // 80000/32 = 2500, exact
    ipm_fused_kernel<<<nblocks, 256>>>(images, Ks, RTs, out);
}

// round 7
// speedup vs baseline: 1.2215x; 1.2215x over previous
#include <cuda_runtime.h>
#include <float.h>
#include <math.h>

// Problem constants (from reference)
#define BEV_N   200          // BEV_H == BEV_W == 200
#define IMG_H   128
#define IMG_W   352
#define NCH     32
#define NB      2            // batch
#define NCAM    6            // cameras per batch
#define BNMAT   (NB*NCAM)    // 12 projection matrices
#define NCELL   (NB*BEV_N*BEV_N)   // 80,000
#define CELLS_PER_BLOCK 32   // 256 threads / 8 lanes-per-cell
#define ROWSTRIDE (IMG_W * (NCH/4))
#define GRID_STEP 0.50251256281407031975f   // 100/199 rounded to fp32

// One fused kernel:
//  Phase 0: reduced P = (K@RT) rows 0..2, cols {0,1,3} into smem (z==0 plane)
//  Phase 1: one thread per (cell,cam); warp-local ballot-compaction of valid cams
//  Phase 2: 8 lanes/cell (float4 channels) sample only the valid cams
__global__ __launch_bounds__(256) void ipm_fused_kernel(const float* __restrict__ images,
                                                        const float* __restrict__ Ks,
                                                        const float* __restrict__ RTs,
                                                        float* __restrict__ out) {
    __shared__ float  sP[BNMAT][9];
    __shared__ float4 sW[CELLS_PER_BLOCK * NCAM];     // (w00,w01,w10,w11)
    __shared__ int    sBase[CELLS_PER_BLOCK * NCAM];  // float4-index of im00

    const int t = threadIdx.x;

    // ---------- Phase 0: projection matrices ----------
    if (t < BNMAT * 9) {
        const int m  = t / 9;
        const int e  = t - m * 9;
        const int r  = e / 3;
        const int ci = e - r * 3;
        const int c  = (ci == 2) ? 3 : ci;
        const float* K  = Ks  + m * 16 + r * 4;
        const float* RT = RTs + m * 16;
        sP[m][e] = K[0] * RT[c] + K[1] * RT[4 + c]
                 + K[2] * RT[8 + c] + K[3] * RT[12 + c];
    }
    __syncthreads();

    const int cell0 = blockIdx.x * CELLS_PER_BLOCK;   // grid is exactly 2500 blocks
    const int lc    = t >> 3;                          // local cell 0..31
    const int sub   = t & 7;                           // lane-in-cell / cam slot

    // ---------- Phase 1: project + warp-local compaction of valid cameras ----------
    int n;                                             // valid-cam count for this cell
    {
        const int cam  = sub;                          // cams 0..5 active, 6..7 idle
        const int cell = cell0 + lc;
        bool valid = false;
        float4 w = make_float4(0.f, 0.f, 0.f, 0.f);
        int baseIdx = 0;

        if (cam < NCAM) {
            const int b   = cell / (BEV_N * BEV_N);
            const int rem = cell - b * (BEV_N * BEV_N);
            const int i   = rem / BEV_N;
            const int j   = rem - i * BEV_N;
            // linspace(-50,50,200) in fp32 (≤1 ulp vs numpy's f64->f32; NO fp64 pipe)
            const float y = fmaf((float)i, GRID_STEP, -50.0f);
            const float x = fmaf((float)j, GRID_STEP, -50.0f);

            const int bn = b * NCAM + cam;
            const float* P = sP[bn];
            const float pc0 = P[0] * y + P[1] * x + P[2];
            const float pc1 = P[3] * y + P[4] * x + P[5];
            const float pc2 = P[6] * y + P[7] * x + P[8];
            const float inv = 1.0f / (pc2 + 1e-7f);
            const float fx = pc0 * inv;
            const float fy = pc1 * inv;

            // Outside [0,W-1) x [0,H-1): clamped bilinear collapses => exact 0
            if (fx >= 0.0f && fx < (float)(IMG_W - 1) &&
                fy >= 0.0f && fy < (float)(IMG_H - 1)) {
                valid = true;
                const float x0f = floorf(fx);
                const float y0f = floorf(fy);
                const float wx1 = fx - x0f, wx0 = 1.0f - wx1;
                const float wy1 = fy - y0f, wy0 = 1.0f - wy1;
                w = make_float4(wx0 * wy0, wx0 * wy1, wx1 * wy0, wx1 * wy1);
                baseIdx = (((int)(bn * IMG_H) + (int)y0f) * IMG_W + (int)x0f) * (NCH / 4);
            }
        }

        const unsigned ball = __ballot_sync(0xFFFFFFFFu, valid);
        const int laneBase  = (t & 31) & ~7;                      // first lane of 8-group
        const unsigned grp  = (ball >> laneBase) & 0xFFu;
        if (valid) {
            const int slot = __popc(grp & ((1u << sub) - 1u));    // cam-ordered slot
            sW[lc * NCAM + slot]    = w;
            sBase[lc * NCAM + slot] = baseIdx;
        }
        n = (int)__popc(grp);
    }
    __syncwarp();   // phase 1 writes and phase 2 reads are warp-local (same 4 cells)

    // ---------- Phase 2: sample valid cams, max-reduce ----------
    // If every cam is valid the result is max over the 6 samples; otherwise some cam
    // contributes an exact 0 (clamp-collapsed weights), so seed with 0.
    float4 best = (n == NCAM)
        ? make_float4(-FLT_MAX, -FLT_MAX, -FLT_MAX, -FLT_MAX)
        : make_float4(0.f, 0.f, 0.f, 0.f);

    const float4* __restrict__ img4 = (const float4*)images;
    const int slot0 = lc * NCAM;

    for (int k = 0; k < n; k++) {
        const float4 w   = sW[slot0 + k];
        const int   base = sBase[slot0 + k] + sub;
        const float4 v00 = __ldg(img4 + base);
        const float4 v10 = __ldg(img4 + base + (NCH / 4));
        const float4 v01 = __ldg(img4 + base + ROWSTRIDE);
        const float4 v11 = __ldg(img4 + base + ROWSTRIDE + (NCH / 4));

        float4 v;
        v.x = w.x * v00.x + w.y * v01.x + w.z * v10.x + w.w * v11.x;
        v.y = w.x * v00.y + w.y * v01.y + w.z * v10.y + w.w * v11.y;
        v.z = w.x * v00.z + w.y * v01.z + w.z * v10.z + w.w * v11.z;
        v.w = w.x * v00.w + w.y * v01.w + w.z * v10.w + w.w * v11.w;

        best.x = fmaxf(best.x, v.x);
        best.y = fmaxf(best.y, v.y);
        best.z = fmaxf(best.z, v.z);
        best.w = fmaxf(best.w, v.w);
    }

    ((float4*)out)[(size_t)(cell0 + lc) * (NCH / 4) + sub] = best;
}

extern "C" void kernel_launch(void* const* d_in, const int* in_sizes, int n_in,
                              void* d_out, int out_size) {
    const float* images = (const float*)d_in[0];
    const float* Ks     = (const float*)d_in[1];
    const float* RTs    = (const float*)d_in[2];
    float* out = (float*)d_out;

    const int nblocks = NCELL / CELLS_PER_BLOCK;   // 80000/32 = 2500, exact
    ipm_fused_kernel<<<nblocks, 256>>>(images, Ks, RTs, out);
}

// round 8
// speedup vs baseline: 1.3409x; 1.0977x over previous
#include <cuda_runtime.h>
#include <float.h>
#include <math.h>

// Problem constants (from reference)
#define BEV_N   200          // BEV_H == BEV_W == 200
#define IMG_H   128
#define IMG_W   352
#define NCH     32
#define NB      2            // batch
#define NCAM    6            // cameras per batch
#define BNMAT   (NB*NCAM)    // 12 projection matrices
#define NPOS    (BEV_N*BEV_N)       // 40,000 positions (per batch)
#define POS_PER_BLOCK 16            // 128 threads / 8 lanes-per-position
#define ROWSTRIDE (IMG_W * (NCH/4))
#define GRID_STEP 0.50251256281407031975f   // 100/199 rounded to fp32

// One fused kernel. Each thread owns ONE position but BOTH batches' cells:
//  Phase 0: reduced P = (K@RT) rows 0..2, cols {0,1,3} into smem (z==0 plane)
//  Phase 1: one thread per (position,cam); projects for batch 0 AND batch 1,
//           warp-local ballot-compaction of valid cams per (position,batch)
//  Phase 2: 8 lanes/position; per iteration issue 8 independent LDG.128
//           (4 corners x 2 batches) -> 2x MLP, fully branchless via zeroed weights
__global__ __launch_bounds__(128) void ipm_fused_kernel(const float* __restrict__ images,
                                                        const float* __restrict__ Ks,
                                                        const float* __restrict__ RTs,
                                                        float* __restrict__ out) {
    __shared__ float  sP[BNMAT][9];
    __shared__ float4 sW[POS_PER_BLOCK][NB][NCAM];    // (w00,w01,w10,w11)
    __shared__ int    sBase[POS_PER_BLOCK][NB][NCAM]; // float4-index of im00 (pixel base)

    const int t = threadIdx.x;

    // ---------- Phase 0: projection matrices ----------
    if (t < BNMAT * 9) {
        const int m  = t / 9;
        const int e  = t - m * 9;
        const int r  = e / 3;
        const int ci = e - r * 3;
        const int c  = (ci == 2) ? 3 : ci;
        const float* K  = Ks  + m * 16 + r * 4;
        const float* RT = RTs + m * 16;
        sP[m][e] = K[0] * RT[c] + K[1] * RT[4 + c]
                 + K[2] * RT[8 + c] + K[3] * RT[12 + c];
    }
    __syncthreads();

    const int pos = t >> 3;                            // local position 0..15
    const int sub = t & 7;                             // lane-in-position / cam slot
    const int p   = blockIdx.x * POS_PER_BLOCK + pos;  // global position, grid exact

    const int i = p / BEV_N;
    const int j = p - i * BEV_N;
    // linspace(-50,50,200) in fp32 (<=1 ulp vs numpy's f64->f32; NO fp64 pipe)
    const float y = fmaf((float)i, GRID_STEP, -50.0f);
    const float x = fmaf((float)j, GRID_STEP, -50.0f);

    // ---------- Phase 1: project both batches + warp-local compaction ----------
    int nA, nB;
    {
        const int cam = sub;                           // cams 0..5 active, 6..7 idle
        bool vA = false, vB = false;
        float4 wA = make_float4(0.f, 0.f, 0.f, 0.f), wB = wA;
        int bA = 0, bB = 0;

        if (cam < NCAM) {
            #pragma unroll
            for (int ba = 0; ba < NB; ba++) {
                const int bn = ba * NCAM + cam;
                const float* P = sP[bn];
                const float pc0 = P[0] * y + P[1] * x + P[2];
                const float pc1 = P[3] * y + P[4] * x + P[5];
                const float pc2 = P[6] * y + P[7] * x + P[8];
                const float inv = 1.0f / (pc2 + 1e-7f);
                const float fx = pc0 * inv;
                const float fy = pc1 * inv;
                // Outside [0,W-1) x [0,H-1): clamped bilinear collapses => exact 0
                if (fx >= 0.0f && fx < (float)(IMG_W - 1) &&
                    fy >= 0.0f && fy < (float)(IMG_H - 1)) {
                    const float x0f = floorf(fx);
                    const float y0f = floorf(fy);
                    const float wx1 = fx - x0f, wx0 = 1.0f - wx1;
                    const float wy1 = fy - y0f, wy0 = 1.0f - wy1;
                    const float4 w = make_float4(wx0 * wy0, wx0 * wy1,
                                                 wx1 * wy0, wx1 * wy1);
                    const int base = ((bn * IMG_H + (int)y0f) * IMG_W + (int)x0f) * (NCH / 4);
                    if (ba == 0) { vA = true; wA = w; bA = base; }
                    else         { vB = true; wB = w; bB = base; }
                }
            }
        }

        const unsigned ballA = __ballot_sync(0xFFFFFFFFu, vA);
        const unsigned ballB = __ballot_sync(0xFFFFFFFFu, vB);
        const int laneBase   = (t & 31) & ~7;                   // first lane of 8-group
        const unsigned grpA  = (ballA >> laneBase) & 0xFFu;
        const unsigned grpB  = (ballB >> laneBase) & 0xFFu;
        const unsigned below = (1u << sub) - 1u;
        if (vA) {
            const int slot = __popc(grpA & below);              // cam-ordered slot
            sW[pos][0][slot] = wA;  sBase[pos][0][slot] = bA;
        }
        if (vB) {
            const int slot = __popc(grpB & below);
            sW[pos][1][slot] = wB;  sBase[pos][1][slot] = bB;
        }
        nA = (int)__popc(grpA);
        nB = (int)__popc(grpB);
    }
    __syncwarp();   // phase 1 writes / phase 2 reads are warp-local (same positions)

    // ---------- Phase 2: branchless paired sampling, max-reduce ----------
    // If every cam is valid the result is max over the 6 samples; otherwise some
    // cam contributes an exact 0 (clamp-collapsed weights), so seed with 0.
    float4 bestA = (nA == NCAM)
        ? make_float4(-FLT_MAX, -FLT_MAX, -FLT_MAX, -FLT_MAX)
        : make_float4(0.f, 0.f, 0.f, 0.f);
    float4 bestB = (nB == NCAM)
        ? make_float4(-FLT_MAX, -FLT_MAX, -FLT_MAX, -FLT_MAX)
        : make_float4(0.f, 0.f, 0.f, 0.f);

    const float4* __restrict__ img4 = (const float4*)images;
    const int nmax = (nA > nB) ? nA : nB;
    const float4 zero4 = make_float4(0.f, 0.f, 0.f, 0.f);

    #pragma unroll 1
    for (int k = 0; k < nmax; k++) {
        const bool okA = (k < nA), okB = (k < nB);
        const int  kA  = okA ? k : 0, kB = okB ? k : 0;
        // Inactive side: weight := 0 (exact-zero contribution), base := 0 (safe addr)
        float4 wA = sW[pos][0][kA];  int baA = okA ? sBase[pos][0][kA] : 0;
        float4 wB = sW[pos][1][kB];  int baB = okB ? sBase[pos][1][kB] : 0;
        if (!okA) wA = zero4;
        if (!okB) wB = zero4;

        const float4* pa = img4 + baA + sub;
        const float4* pb = img4 + baB + sub;
        // 8 independent loads in flight before any consume
        const float4 a00 = __ldg(pa);
        const float4 a10 = __ldg(pa + (NCH / 4));
        const float4 a01 = __ldg(pa + ROWSTRIDE);
        const float4 a11 = __ldg(pa + ROWSTRIDE + (NCH / 4));
        const float4 b00 = __ldg(pb);
        const float4 b10 = __ldg(pb + (NCH / 4));
        const float4 b01 = __ldg(pb + ROWSTRIDE);
        const float4 b11 = __ldg(pb + ROWSTRIDE + (NCH / 4));

        float4 v;
        v.x = wA.x * a00.x + wA.y * a01.x + wA.z * a10.x + wA.w * a11.x;
        v.y = wA.x * a00.y + wA.y * a01.y + wA.z * a10.y + wA.w * a11.y;
        v.z = wA.x * a00.z + wA.y * a01.z + wA.z * a10.z + wA.w * a11.z;
        v.w = wA.x * a00.w + wA.y * a01.w + wA.z * a10.w + wA.w * a11.w;
        bestA.x = fmaxf(bestA.x, v.x);
        bestA.y = fmaxf(bestA.y, v.y);
        bestA.z = fmaxf(bestA.z, v.z);
        bestA.w = fmaxf(bestA.w, v.w);

        v.x = wB.x * b00.x + wB.y * b01.x + wB.z * b10.x + wB.w * b11.x;
        v.y = wB.x * b00.y + wB.y * b01.y + wB.z * b10.y + wB.w * b11.y;
        v.z = wB.x * b00.z + wB.y * b01.z + wB.z * b10.z + wB.w * b11.z;
        v.w = wB.x * b00.w + wB.y * b01.w + wB.z * b10.w + wB.w * b11.w;
        bestB.x = fmaxf(bestB.x, v.x);
        bestB.y = fmaxf(bestB.y, v.y);
        bestB.z = fmaxf(bestB.z, v.z);
        bestB.w = fmaxf(bestB.w, v.w);
    }

    float4* out4 = (float4*)out;
    out4[(size_t)p * (NCH / 4) + sub]          = bestA;   // batch 0 cell
    out4[(size_t)(NPOS + p) * (NCH / 4) + sub] = bestB;   // batch 1 cell
}

extern "C" void kernel_launch(void* const* d_in, const int* in_sizes, int n_in,
                              void* d_out, int out_size) {
    const float* images = (const float*)d_in[0];
    const float* Ks     = (const float*)d_in[1];
    const float* RTs    = (const float*)d_in[2];
    float* out = (float*)d_out;

    const int nblocks = NPOS / POS_PER_BLOCK;   // 40000/16 = 2500, exact
    ipm_fused_kernel<<<nblocks, 128>>>(images, Ks, RTs, out);
}